// round 14
// baseline (speedup 1.0000x reference)
#include <cuda_runtime.h>
#include <cuda_bf16.h>
#include <cuda_fp16.h>

#define BATCH      1024
#define INPUT_DIM  1024
#define NB_K       32
#define KDIM       16
#define OUT_COLS   (INPUT_DIM + NB_K)   // 1056
#define NTILE      8                    // 8 b-tiles of 128 (pairwise)
#define NPAIRS     36                   // i<=j tile pairs

__device__ __half2      g_acth[(size_t)NB_K * BATCH * 8];            // 1 MB
__device__ float        g_pp  [(size_t)NB_K * NTILE * NTILE * 128];  // 1 MB
__device__ unsigned int g_wtbf[(size_t)NB_K * KDIM * INPUT_DIM / 2]; // Wt bf16
__device__ unsigned int g_cnt [NB_K];                                // pair-completion counters

__constant__ int2 c_pairs[NPAIRS] = {
    {0,0},{0,1},{0,2},{0,3},{0,4},{0,5},{0,6},{0,7},
          {1,1},{1,2},{1,3},{1,4},{1,5},{1,6},{1,7},
                {2,2},{2,3},{2,4},{2,5},{2,6},{2,7},
                      {3,3},{3,4},{3,5},{3,6},{3,7},
                            {4,4},{4,5},{4,6},{4,7},
                                  {5,5},{5,6},{5,7},
                                        {6,6},{6,7},
                                              {7,7}
};

#define MMA_BF16(c0,c1,c2,c3,a0,a1,a2,a3,b0,b1) \
    asm("mma.sync.aligned.m16n8k16.row.col.f32.bf16.bf16.f32 " \
        "{%0,%1,%2,%3}, {%4,%5,%6,%7}, {%8,%9}, {%0,%1,%2,%3};" \
        : "+f"(c0), "+f"(c1), "+f"(c2), "+f"(c3) \
        : "r"(a0), "r"(a1), "r"(a2), "r"(a3), "r"(b0), "r"(b1))

// ---------------------------------------------------------------------------
// Kernel 0: W convert+transpose, 128 blocks (k = bx>>2, d-quarter = bx&3).
// Also resets the per-k completion counters used by the pairwise kernel.
// ---------------------------------------------------------------------------
__global__ void __launch_bounds__(256) mbd_wconvert_kernel(
    const float* __restrict__ W)
{
    __shared__ unsigned short swt[16 * 256];    // 8 KB: [m][d_local]
    const int tid = threadIdx.x;
    const int k   = blockIdx.x >> 2;
    const int dq  = blockIdx.x & 3;             // d-quarter: 256 d's

    if (blockIdx.x < NB_K && tid == 0) g_cnt[blockIdx.x] = 0u;

    // read W[k][dq*256 .. +256][0..16] = 1024 float4, 4 per thread
    const float4* wk4 = reinterpret_cast<const float4*>(
        W + (size_t)k * INPUT_DIM * KDIM + (size_t)dq * 256 * KDIM);
#pragma unroll
    for (int i = 0; i < 4; i++) {
        int idx = tid + i * 256;                // float4 idx within chunk
        int base = idx * 4;
        int d = base >> 4;                      // 0..255
        int m = base & 15;
        float4 v = wk4[idx];
        swt[(m + 0) * 256 + d] = __bfloat16_as_ushort(__float2bfloat16(v.x));
        swt[(m + 1) * 256 + d] = __bfloat16_as_ushort(__float2bfloat16(v.y));
        swt[(m + 2) * 256 + d] = __bfloat16_as_ushort(__float2bfloat16(v.z));
        swt[(m + 3) * 256 + d] = __bfloat16_as_ushort(__float2bfloat16(v.w));
    }
    __syncthreads();

    // write Wt[k][m][dq*128 uints .. +128]: 16 m-rows x 128 uints, 8/thread
    const unsigned int* s = reinterpret_cast<const unsigned int*>(swt);
#pragma unroll
    for (int i = 0; i < 8; i++) {
        int idx = tid + i * 256;                // 0..2047
        int m = idx >> 7;
        int c = idx & 127;
        g_wtbf[(size_t)k * 8192 + m * 512 + dq * 128 + c] = s[m * 128 + c];
    }
}

// ---------------------------------------------------------------------------
// Kernel A: tensor-core GEMM (bf16 MMA, fp32 acc -> fp16 out) + folded x-copy.
// grid = (8 k-groups, 64 b-tiles of 16) = 512 blocks, block = 128 (4 warps).
// ---------------------------------------------------------------------------
__global__ void __launch_bounds__(128) mbd_gemm_kernel(
    const float* __restrict__ x, float* __restrict__ out)
{
    __shared__ unsigned int sxs[16 * 516];      // 33 KB, pitch 516 uints/row

    const int tid  = threadIdx.x;
    const int lane = tid & 31;
    const int w    = tid >> 5;
    const int k    = blockIdx.x * 4 + w;
    const int b0   = blockIdx.y * 16;
    const int g    = lane >> 2;
    const int tig  = lane & 3;

    // ---- folded x-copy: 512 blocks x 512 float4 covers all of x ----
    {
        const int flat = blockIdx.y * 8 + blockIdx.x;    // 0..511
        const float4* x4 = reinterpret_cast<const float4*>(x);
        float4*       o4 = reinterpret_cast<float4*>(out);
#pragma unroll
        for (int i = 0; i < 4; i++) {
            int idx = flat * 512 + tid + i * 128;
            int r = idx >> 8;
            int c = idx & 255;
            o4[(size_t)r * (OUT_COLS / 4) + c] = x4[idx];
        }
    }

    // stage x tile: read fp32, convert to bf16 inline
    {
        const float4* x4 = reinterpret_cast<const float4*>(x);
#pragma unroll
        for (int i = 0; i < 32; i++) {
            int idx = tid + i * 128;
            int r = idx >> 8;
            int c = idx & 255;
            float4 v = x4[(size_t)(b0 + r) * 256 + c];
            __nv_bfloat162 lo = __floats2bfloat162_rn(v.x, v.y);
            __nv_bfloat162 hi = __floats2bfloat162_rn(v.z, v.w);
            uint2 o;
            o.x = *reinterpret_cast<unsigned int*>(&lo);
            o.y = *reinterpret_cast<unsigned int*>(&hi);
            *reinterpret_cast<uint2*>(sxs + r * 516 + 2 * c) = o;
        }
    }
    __syncthreads();

    float c0 = 0.f, c1 = 0.f, c2 = 0.f, c3 = 0.f;
    float c4 = 0.f, c5 = 0.f, c6 = 0.f, c7 = 0.f;

    const unsigned int* bw = g_wtbf + (size_t)k * 8192;
    const int ia_base = g * 516 + tig;
    const int ib_base = g * 512 + tig;

#pragma unroll 4
    for (int d0 = 0; d0 < 512; d0 += 8) {
        unsigned int a0 = sxs[ia_base + d0];
        unsigned int a1 = sxs[ia_base + d0 + 8 * 516];
        unsigned int a2 = sxs[ia_base + d0 + 4];
        unsigned int a3 = sxs[ia_base + d0 + 4 + 8 * 516];
        unsigned int b00 = bw[ib_base + d0];
        unsigned int b01 = bw[ib_base + d0 + 4];
        unsigned int b10 = bw[ib_base + d0 + 8 * 512];
        unsigned int b11 = bw[ib_base + d0 + 8 * 512 + 4];
        MMA_BF16(c0, c1, c2, c3, a0, a1, a2, a3, b00, b01);
        MMA_BF16(c4, c5, c6, c7, a0, a1, a2, a3, b10, b11);
    }

    __half2* o1 = g_acth + ((size_t)k * BATCH + b0 + g) * 8;
    __half2* o2 = o1 + 8 * 8;
    o1[tig]     = __float22half2_rn(make_float2(c0, c1));
    o1[4 + tig] = __float22half2_rn(make_float2(c4, c5));
    o2[tig]     = __float22half2_rn(make_float2(c2, c3));
    o2[4 + tig] = __float22half2_rn(make_float2(c6, c7));
}

// ---------------------------------------------------------------------------
// Kernel B: symmetric pairwise (half2, 2 cols/iter, dual h2exp, packed shfl)
// + in-kernel feature assembly: the LAST finishing block of each k sums
// g_pp[k] into out (fixed j-order loop -> deterministic result).
// ---------------------------------------------------------------------------
__global__ void __launch_bounds__(256) mbd_pairwise_kernel(float* __restrict__ out)
{
    const int k    = blockIdx.x;
    const int tid  = threadIdx.x;
    const int lane = tid & 31;
    const int w    = tid >> 5;
    const int bsub = w & 3;
    const int ch   = w >> 2;
    const int2 pr  = c_pairs[blockIdx.y];
    const int i_t  = pr.x, j_t = pr.y;
    const bool diag = (i_t == j_t);

    __shared__ uint4 sA[128 * 2];
    __shared__ uint4 sB[128 * 2];
    __shared__ float scol[8][64];
    __shared__ float srow[256];
    __shared__ unsigned int sdone;

    const uint4* actk = reinterpret_cast<const uint4*>(
        g_acth + (size_t)k * BATCH * 8);

    sA[tid] = actk[(size_t)i_t * 256 + tid];
    sB[tid] = actk[(size_t)j_t * 256 + tid];
    reinterpret_cast<float*>(scol)[tid]       = 0.f;
    reinterpret_cast<float*>(scol)[tid + 256] = 0.f;
    __syncthreads();

    const int bl = bsub * 32 + lane;
    __half2 a[8];
    {
        uint4 p0 = sA[bl * 2 + 0];
        uint4 p1 = sA[bl * 2 + 1];
        a[0] = *reinterpret_cast<__half2*>(&p0.x);
        a[1] = *reinterpret_cast<__half2*>(&p0.y);
        a[2] = *reinterpret_cast<__half2*>(&p0.z);
        a[3] = *reinterpret_cast<__half2*>(&p0.w);
        a[4] = *reinterpret_cast<__half2*>(&p1.x);
        a[5] = *reinterpret_cast<__half2*>(&p1.y);
        a[6] = *reinterpret_cast<__half2*>(&p1.z);
        a[7] = *reinterpret_cast<__half2*>(&p1.w);
    }

    float f = 0.f;
    const int c_beg = ch * 64;

#define HAD(x, y) __habs2(__hsub2(x, y))
#define H2(u) (*reinterpret_cast<const __half2*>(&(u)))

#pragma unroll 4
    for (int cc = 0; cc < 32; cc++) {
        const int c0 = c_beg + 2 * cc;
        uint4 p0 = sB[c0 * 2 + 0];
        uint4 p1 = sB[c0 * 2 + 1];
        uint4 q0 = sB[c0 * 2 + 2];
        uint4 q1 = sB[c0 * 2 + 3];

        __half2 t0 = __hadd2(HAD(a[0], H2(p0.x)), HAD(a[1], H2(p0.y)));
        __half2 t1 = __hadd2(HAD(a[2], H2(p0.z)), HAD(a[3], H2(p0.w)));
        __half2 t2 = __hadd2(HAD(a[4], H2(p1.x)), HAD(a[5], H2(p1.y)));
        __half2 t3 = __hadd2(HAD(a[6], H2(p1.z)), HAD(a[7], H2(p1.w)));
        t0 = __hadd2(__hadd2(t0, t1), __hadd2(t2, t3));
        __half2 u0 = __hadd2(HAD(a[0], H2(q0.x)), HAD(a[1], H2(q0.y)));
        __half2 u1 = __hadd2(HAD(a[2], H2(q0.z)), HAD(a[3], H2(q0.w)));
        __half2 u2 = __hadd2(HAD(a[4], H2(q1.x)), HAD(a[5], H2(q1.y)));
        __half2 u3 = __hadd2(HAD(a[6], H2(q1.z)), HAD(a[7], H2(q1.w)));
        u0 = __hadd2(__hadd2(u0, u1), __hadd2(u2, u3));

        __half2 s2 = __hadd2(__lows2half2(t0, u0), __highs2half2(t0, u0));
        __half2 e2 = h2exp(__hneg2(s2));
        float2 ef = __half22float2(e2);
        f += ef.x + ef.y;

        if (!diag) {
            unsigned int ev = *reinterpret_cast<unsigned int*>(&e2);
#pragma unroll
            for (int m = 16; m >= 1; m >>= 1) {
                unsigned int ov = __shfl_xor_sync(0xffffffffu, ev, m);
                __half2 sum = __hadd2(*reinterpret_cast<__half2*>(&ev),
                                      *reinterpret_cast<__half2*>(&ov));
                ev = *reinterpret_cast<unsigned int*>(&sum);
            }
            if (lane == 0) {
                float2 cf = __half22float2(*reinterpret_cast<__half2*>(&ev));
                scol[w][2 * cc]     += cf.x;
                scol[w][2 * cc + 1] += cf.y;
            }
        }
    }
#undef HAD
#undef H2

    srow[tid] = f;
    __syncthreads();

    if (tid < 128) {
        float rt = srow[tid] + srow[tid + 128];
        g_pp[(((size_t)k * NTILE + i_t) * NTILE + j_t) * 128 + tid] = rt;
    }
    if (!diag && tid < 128) {
        const int c   = tid;
        const int cch = c >> 6;
        const int cl  = c & 63;
        float ct = scol[cch * 4 + 0][cl] + scol[cch * 4 + 1][cl]
                 + scol[cch * 4 + 2][cl] + scol[cch * 4 + 3][cl];
        g_pp[(((size_t)k * NTILE + j_t) * NTILE + i_t) * 128 + c] = ct;
    }

    // ---- last finishing block of this k assembles its features ----
    __threadfence();
    __syncthreads();
    if (tid == 0) sdone = atomicInc(&g_cnt[k], 0xffffffffu);
    __syncthreads();
    if (sdone == NPAIRS - 1) {
#pragma unroll
        for (int q = 0; q < 4; q++) {
            const int b = tid + q * 256;
            const int t = b >> 7;
            const int r = b & 127;
            const float* pp = g_pp + (((size_t)k * NTILE + t) * NTILE) * 128 + r;
            float s = 0.f;
#pragma unroll
            for (int j = 0; j < NTILE; j++)
                s += pp[j * 128];
            out[(size_t)b * OUT_COLS + INPUT_DIM + k] = s;
        }
    }
}

extern "C" void kernel_launch(void* const* d_in, const int* in_sizes, int n_in,
                              void* d_out, int out_size)
{
    (void)in_sizes; (void)n_in; (void)out_size;
    const float* x = (const float*)d_in[0];
    const float* W = (const float*)d_in[1];
    float* out = (float*)d_out;

    mbd_wconvert_kernel<<<NB_K * 4, 256>>>(W);
    mbd_gemm_kernel<<<dim3(NB_K / 4, BATCH / 16), 128>>>(x, out);
    mbd_pairwise_kernel<<<dim3(NB_K, NPAIRS), 256>>>(out);
}

// round 15
// speedup vs baseline: 1.0245x; 1.0245x over previous
#include <cuda_runtime.h>
#include <cuda_bf16.h>
#include <cuda_fp16.h>

#define BATCH      1024
#define INPUT_DIM  1024
#define NB_K       32
#define KDIM       16
#define OUT_COLS   (INPUT_DIM + NB_K)   // 1056
#define NTILE      8                    // 8 b-tiles of 128 (pairwise)
#define NPAIRS     36                   // i<=j tile pairs

__device__ __half2      g_acth[(size_t)NB_K * BATCH * 8];            // 1 MB
__device__ float        g_pp  [(size_t)NB_K * NTILE * NTILE * 128];  // 1 MB
__device__ unsigned int g_wtbf[(size_t)NB_K * KDIM * INPUT_DIM / 2]; // Wt bf16
__device__ unsigned int g_flag;                                      // convert-done counter

__constant__ int2 c_pairs[NPAIRS] = {
    {0,0},{0,1},{0,2},{0,3},{0,4},{0,5},{0,6},{0,7},
          {1,1},{1,2},{1,3},{1,4},{1,5},{1,6},{1,7},
                {2,2},{2,3},{2,4},{2,5},{2,6},{2,7},
                      {3,3},{3,4},{3,5},{3,6},{3,7},
                            {4,4},{4,5},{4,6},{4,7},
                                  {5,5},{5,6},{5,7},
                                        {6,6},{6,7},
                                              {7,7}
};

#define MMA_BF16(c0,c1,c2,c3,a0,a1,a2,a3,b0,b1) \
    asm("mma.sync.aligned.m16n8k16.row.col.f32.bf16.bf16.f32 " \
        "{%0,%1,%2,%3}, {%4,%5,%6,%7}, {%8,%9}, {%0,%1,%2,%3};" \
        : "+f"(c0), "+f"(c1), "+f"(c2), "+f"(c3) \
        : "r"(a0), "r"(a1), "r"(a2), "r"(a3), "r"(b0), "r"(b1))

// ---------------------------------------------------------------------------
// Kernel A (fused): W convert (blocks 0..127) + x-copy + tensor-core GEMM.
// grid = 512 blocks x 128 threads; ALL blocks resident in one wave
// (smem 33KB -> ~6 blocks/SM), so the producer spin-wait cannot deadlock.
// Order per block: [convert W quarter if bid<128 -> flag] ; x-copy ;
// spin(flag==128) ; stage x bf16 ; 64 MMA k-steps ; write g_acth fp16.
// ---------------------------------------------------------------------------
__global__ void __launch_bounds__(128) mbd_gemm_kernel(
    const float* __restrict__ x, const float* __restrict__ W,
    float* __restrict__ out)
{
    __shared__ unsigned int sxs[16 * 516];      // 33 KB; reused for W staging

    const int bid  = blockIdx.x;                // 0..511
    const int tid  = threadIdx.x;
    const int lane = tid & 31;
    const int w    = tid >> 5;
    const int kg   = bid & 7;                   // k-group
    const int bt   = bid >> 3;                  // b-tile
    const int k    = kg * 4 + w;
    const int b0   = bt * 16;
    const int g    = lane >> 2;
    const int tig  = lane & 3;

    // ---- phase 1: blocks 0..127 convert one W d-quarter to Wt bf16 ----
    if (bid < 128) {
        unsigned short* swt = reinterpret_cast<unsigned short*>(sxs); // 8 KB
        const int kc = bid >> 2;
        const int dq = bid & 3;
        const float4* wk4 = reinterpret_cast<const float4*>(
            W + (size_t)kc * INPUT_DIM * KDIM + (size_t)dq * 256 * KDIM);
#pragma unroll
        for (int i = 0; i < 8; i++) {
            int idx = tid + i * 128;            // 0..1023 float4
            int base = idx * 4;
            int d = base >> 4;                  // 0..255
            int m = base & 15;
            float4 v = wk4[idx];
            swt[(m + 0) * 256 + d] = __bfloat16_as_ushort(__float2bfloat16(v.x));
            swt[(m + 1) * 256 + d] = __bfloat16_as_ushort(__float2bfloat16(v.y));
            swt[(m + 2) * 256 + d] = __bfloat16_as_ushort(__float2bfloat16(v.z));
            swt[(m + 3) * 256 + d] = __bfloat16_as_ushort(__float2bfloat16(v.w));
        }
        __syncthreads();
        const unsigned int* s = reinterpret_cast<const unsigned int*>(swt);
#pragma unroll
        for (int i = 0; i < 16; i++) {
            int idx = tid + i * 128;            // 0..2047
            int m = idx >> 7;
            int c = idx & 127;
            g_wtbf[(size_t)kc * 8192 + m * 512 + dq * 128 + c] = s[m * 128 + c];
        }
        __threadfence();
        __syncthreads();
        if (tid == 0) atomicAdd(&g_flag, 1u);
    }

    // ---- phase 2: x-copy (independent of conversion; overlaps it) ----
    {
        const float4* x4 = reinterpret_cast<const float4*>(x);
        float4*       o4 = reinterpret_cast<float4*>(out);
#pragma unroll
        for (int i = 0; i < 4; i++) {
            int idx = bid * 512 + tid + i * 128;
            int r = idx >> 8;
            int c = idx & 255;
            o4[(size_t)r * (OUT_COLS / 4) + c] = x4[idx];
        }
    }

    // ---- phase 3: wait for all 128 conversion blocks ----
    if (tid == 0) {
        while (atomicAdd(&g_flag, 0u) < 128u) { }
    }
    __syncthreads();

    // ---- phase 4: stage x tile as bf16 (16 rows, pitch 516 uints) ----
    {
        const float4* x4 = reinterpret_cast<const float4*>(x);
#pragma unroll
        for (int i = 0; i < 32; i++) {
            int idx = tid + i * 128;
            int r = idx >> 8;
            int c = idx & 255;
            float4 v = x4[(size_t)(b0 + r) * 256 + c];
            __nv_bfloat162 lo = __floats2bfloat162_rn(v.x, v.y);
            __nv_bfloat162 hi = __floats2bfloat162_rn(v.z, v.w);
            uint2 o;
            o.x = *reinterpret_cast<unsigned int*>(&lo);
            o.y = *reinterpret_cast<unsigned int*>(&hi);
            *reinterpret_cast<uint2*>(sxs + r * 516 + 2 * c) = o;
        }
    }
    __syncthreads();

    // ---- phase 5: MMA over d (64 k16-steps) ----
    float c0 = 0.f, c1 = 0.f, c2 = 0.f, c3 = 0.f;
    float c4 = 0.f, c5 = 0.f, c6 = 0.f, c7 = 0.f;

    const unsigned int* bw = g_wtbf + (size_t)k * 8192;
    const int ia_base = g * 516 + tig;
    const int ib_base = g * 512 + tig;

#pragma unroll 4
    for (int d0 = 0; d0 < 512; d0 += 8) {
        unsigned int a0 = sxs[ia_base + d0];
        unsigned int a1 = sxs[ia_base + d0 + 8 * 516];
        unsigned int a2 = sxs[ia_base + d0 + 4];
        unsigned int a3 = sxs[ia_base + d0 + 4 + 8 * 516];
        unsigned int b00 = bw[ib_base + d0];
        unsigned int b01 = bw[ib_base + d0 + 4];
        unsigned int b10 = bw[ib_base + d0 + 8 * 512];
        unsigned int b11 = bw[ib_base + d0 + 8 * 512 + 4];
        MMA_BF16(c0, c1, c2, c3, a0, a1, a2, a3, b00, b01);
        MMA_BF16(c4, c5, c6, c7, a0, a1, a2, a3, b10, b11);
    }

    __half2* o1 = g_acth + ((size_t)k * BATCH + b0 + g) * 8;
    __half2* o2 = o1 + 8 * 8;
    o1[tig]     = __float22half2_rn(make_float2(c0, c1));
    o1[4 + tig] = __float22half2_rn(make_float2(c4, c5));
    o2[tig]     = __float22half2_rn(make_float2(c2, c3));
    o2[4 + tig] = __float22half2_rn(make_float2(c6, c7));
}

// ---------------------------------------------------------------------------
// Kernel B: symmetric pairwise (verbatim R13: half2, 2 cols/iter, dual h2exp,
// packed shfl col-reduce). grid = (32 k, 36 tile-pairs), block = 256.
// ---------------------------------------------------------------------------
__global__ void __launch_bounds__(256) mbd_pairwise_kernel()
{
    const int k    = blockIdx.x;
    const int tid  = threadIdx.x;
    const int lane = tid & 31;
    const int w    = tid >> 5;
    const int bsub = w & 3;
    const int ch   = w >> 2;
    const int2 pr  = c_pairs[blockIdx.y];
    const int i_t  = pr.x, j_t = pr.y;
    const bool diag = (i_t == j_t);

    __shared__ uint4 sA[128 * 2];
    __shared__ uint4 sB[128 * 2];
    __shared__ float scol[8][64];
    __shared__ float srow[256];

    const uint4* actk = reinterpret_cast<const uint4*>(
        g_acth + (size_t)k * BATCH * 8);

    sA[tid] = actk[(size_t)i_t * 256 + tid];
    sB[tid] = actk[(size_t)j_t * 256 + tid];
    reinterpret_cast<float*>(scol)[tid]       = 0.f;
    reinterpret_cast<float*>(scol)[tid + 256] = 0.f;
    __syncthreads();

    const int bl = bsub * 32 + lane;
    __half2 a[8];
    {
        uint4 p0 = sA[bl * 2 + 0];
        uint4 p1 = sA[bl * 2 + 1];
        a[0] = *reinterpret_cast<__half2*>(&p0.x);
        a[1] = *reinterpret_cast<__half2*>(&p0.y);
        a[2] = *reinterpret_cast<__half2*>(&p0.z);
        a[3] = *reinterpret_cast<__half2*>(&p0.w);
        a[4] = *reinterpret_cast<__half2*>(&p1.x);
        a[5] = *reinterpret_cast<__half2*>(&p1.y);
        a[6] = *reinterpret_cast<__half2*>(&p1.z);
        a[7] = *reinterpret_cast<__half2*>(&p1.w);
    }

    float f = 0.f;
    const int c_beg = ch * 64;

#define HAD(x, y) __habs2(__hsub2(x, y))
#define H2(u) (*reinterpret_cast<const __half2*>(&(u)))

#pragma unroll 4
    for (int cc = 0; cc < 32; cc++) {
        const int c0 = c_beg + 2 * cc;
        uint4 p0 = sB[c0 * 2 + 0];
        uint4 p1 = sB[c0 * 2 + 1];
        uint4 q0 = sB[c0 * 2 + 2];
        uint4 q1 = sB[c0 * 2 + 3];

        __half2 t0 = __hadd2(HAD(a[0], H2(p0.x)), HAD(a[1], H2(p0.y)));
        __half2 t1 = __hadd2(HAD(a[2], H2(p0.z)), HAD(a[3], H2(p0.w)));
        __half2 t2 = __hadd2(HAD(a[4], H2(p1.x)), HAD(a[5], H2(p1.y)));
        __half2 t3 = __hadd2(HAD(a[6], H2(p1.z)), HAD(a[7], H2(p1.w)));
        t0 = __hadd2(__hadd2(t0, t1), __hadd2(t2, t3));
        __half2 u0 = __hadd2(HAD(a[0], H2(q0.x)), HAD(a[1], H2(q0.y)));
        __half2 u1 = __hadd2(HAD(a[2], H2(q0.z)), HAD(a[3], H2(q0.w)));
        __half2 u2 = __hadd2(HAD(a[4], H2(q1.x)), HAD(a[5], H2(q1.y)));
        __half2 u3 = __hadd2(HAD(a[6], H2(q1.z)), HAD(a[7], H2(q1.w)));
        u0 = __hadd2(__hadd2(u0, u1), __hadd2(u2, u3));

        __half2 s2 = __hadd2(__lows2half2(t0, u0), __highs2half2(t0, u0));
        __half2 e2 = h2exp(__hneg2(s2));
        float2 ef = __half22float2(e2);
        f += ef.x + ef.y;

        if (!diag) {
            unsigned int ev = *reinterpret_cast<unsigned int*>(&e2);
#pragma unroll
            for (int m = 16; m >= 1; m >>= 1) {
                unsigned int ov = __shfl_xor_sync(0xffffffffu, ev, m);
                __half2 sum = __hadd2(*reinterpret_cast<__half2*>(&ev),
                                      *reinterpret_cast<__half2*>(&ov));
                ev = *reinterpret_cast<unsigned int*>(&sum);
            }
            if (lane == 0) {
                float2 cf = __half22float2(*reinterpret_cast<__half2*>(&ev));
                scol[w][2 * cc]     += cf.x;
                scol[w][2 * cc + 1] += cf.y;
            }
        }
    }
#undef HAD
#undef H2

    srow[tid] = f;
    __syncthreads();

    if (tid < 128) {
        float rt = srow[tid] + srow[tid + 128];
        g_pp[(((size_t)k * NTILE + i_t) * NTILE + j_t) * 128 + tid] = rt;
    }
    if (!diag && tid < 128) {
        const int c   = tid;
        const int cch = c >> 6;
        const int cl  = c & 63;
        float ct = scol[cch * 4 + 0][cl] + scol[cch * 4 + 1][cl]
                 + scol[cch * 4 + 2][cl] + scol[cch * 4 + 3][cl];
        g_pp[(((size_t)k * NTILE + j_t) * NTILE + i_t) * 128 + c] = ct;
    }
}

// ---------------------------------------------------------------------------
// Kernel C: assemble features from g_pp; also resets g_flag for next replay
// (runs last every call, so the reset is race-free and graph-deterministic).
// ---------------------------------------------------------------------------
__global__ void __launch_bounds__(256) mbd_assemble_kernel(float* __restrict__ out)
{
    if (blockIdx.x == 0 && threadIdx.x == 0) g_flag = 0u;

    const int gtid = blockIdx.x * 256 + threadIdx.x;   // 0..32767
    const int k = gtid >> 10;
    const int b = gtid & 1023;
    const int t = b >> 7;
    const int r = b & 127;
    const float* pp = g_pp + (((size_t)k * NTILE + t) * NTILE) * 128 + r;
    float s = 0.f;
#pragma unroll
    for (int j = 0; j < NTILE; j++)
        s += pp[j * 128];
    out[(size_t)b * OUT_COLS + INPUT_DIM + k] = s;
}

extern "C" void kernel_launch(void* const* d_in, const int* in_sizes, int n_in,
                              void* d_out, int out_size)
{
    (void)in_sizes; (void)n_in; (void)out_size;
    const float* x = (const float*)d_in[0];
    const float* W = (const float*)d_in[1];
    float* out = (float*)d_out;

    mbd_gemm_kernel<<<512, 128>>>(x, W, out);
    mbd_pairwise_kernel<<<dim3(NB_K, NPAIRS), 256>>>();
    mbd_assemble_kernel<<<NB_K * BATCH / 256, 256>>>(out);
}

// round 16
// speedup vs baseline: 1.0250x; 1.0005x over previous
#include <cuda_runtime.h>
#include <cuda_bf16.h>
#include <cuda_fp16.h>

#define BATCH      1024
#define INPUT_DIM  1024
#define NB_K       32
#define KDIM       16
#define OUT_COLS   (INPUT_DIM + NB_K)   // 1056
#define NTILE      8                    // 8 b-tiles of 128 (pairwise)
#define NPAIRS     36                   // i<=j tile pairs

__device__ __half2      g_acth[(size_t)NB_K * BATCH * 8];            // 1 MB
__device__ float        g_pp  [(size_t)NB_K * NTILE * NTILE * 128];  // 1 MB
__device__ unsigned int g_wtbf[(size_t)NB_K * KDIM * INPUT_DIM / 2]; // Wt bf16 [32][16][512]
__device__ unsigned int g_xbf [(size_t)BATCH * INPUT_DIM / 2];       // x bf16 [1024][512]

__constant__ int2 c_pairs[NPAIRS] = {
    {0,0},{0,1},{0,2},{0,3},{0,4},{0,5},{0,6},{0,7},
          {1,1},{1,2},{1,3},{1,4},{1,5},{1,6},{1,7},
                {2,2},{2,3},{2,4},{2,5},{2,6},{2,7},
                      {3,3},{3,4},{3,5},{3,6},{3,7},
                            {4,4},{4,5},{4,6},{4,7},
                                  {5,5},{5,6},{5,7},
                                        {6,6},{6,7},
                                              {7,7}
};

#define MMA_BF16(c0,c1,c2,c3,a0,a1,a2,a3,b0,b1) \
    asm("mma.sync.aligned.m16n8k16.row.col.f32.bf16.bf16.f32 " \
        "{%0,%1,%2,%3}, {%4,%5,%6,%7}, {%8,%9}, {%0,%1,%2,%3};" \
        : "+f"(c0), "+f"(c1), "+f"(c2), "+f"(c3) \
        : "r"(a0), "r"(a1), "r"(a2), "r"(a3), "r"(b0), "r"(b1))

// ---------------------------------------------------------------------------
// Kernel 0: convert. blocks 0..127: W quarter -> Wt bf16 (verified R14 code).
//           blocks 128..191: 16 x-rows -> g_xbf bf16.
// ---------------------------------------------------------------------------
__global__ void __launch_bounds__(256) mbd_convert_kernel(
    const float* __restrict__ x, const float* __restrict__ W)
{
    __shared__ unsigned short swt[16 * 256];    // 8 KB (W blocks only)
    const int tid = threadIdx.x;

    if (blockIdx.x < 128) {
        const int k  = blockIdx.x >> 2;
        const int dq = blockIdx.x & 3;          // d-quarter: 256 d's
        const float4* wk4 = reinterpret_cast<const float4*>(
            W + (size_t)k * INPUT_DIM * KDIM + (size_t)dq * 256 * KDIM);
#pragma unroll
        for (int i = 0; i < 4; i++) {
            int idx = tid + i * 256;
            int base = idx * 4;
            int d = base >> 4;
            int m = base & 15;
            float4 v = wk4[idx];
            swt[(m + 0) * 256 + d] = __bfloat16_as_ushort(__float2bfloat16(v.x));
            swt[(m + 1) * 256 + d] = __bfloat16_as_ushort(__float2bfloat16(v.y));
            swt[(m + 2) * 256 + d] = __bfloat16_as_ushort(__float2bfloat16(v.z));
            swt[(m + 3) * 256 + d] = __bfloat16_as_ushort(__float2bfloat16(v.w));
        }
        __syncthreads();
        const unsigned int* s = reinterpret_cast<const unsigned int*>(swt);
#pragma unroll
        for (int i = 0; i < 8; i++) {
            int idx = tid + i * 256;
            int m = idx >> 7;
            int c = idx & 127;
            g_wtbf[(size_t)k * 8192 + m * 512 + dq * 128 + c] = s[m * 128 + c];
        }
    } else {
        const int base_row = (blockIdx.x - 128) * 16;
        const float4* x4 = reinterpret_cast<const float4*>(x);
        uint2* o2 = reinterpret_cast<uint2*>(g_xbf);
#pragma unroll
        for (int i = 0; i < 16; i++) {
            int idx = tid + i * 256;            // 0..4095: 16 rows x 256 float4
            int r = idx >> 8;
            int c = idx & 255;
            float4 v = x4[(size_t)(base_row + r) * 256 + c];
            __nv_bfloat162 lo = __floats2bfloat162_rn(v.x, v.y);
            __nv_bfloat162 hi = __floats2bfloat162_rn(v.z, v.w);
            uint2 o;
            o.x = *reinterpret_cast<unsigned int*>(&lo);
            o.y = *reinterpret_cast<unsigned int*>(&hi);
            o2[(size_t)(base_row + r) * 256 + c] = o;
        }
    }
}

// ---------------------------------------------------------------------------
// Kernel A: tensor-core GEMM + folded x-copy.
// grid = (32 k, 8 b-tiles of 128) = 256 blocks, block = 256 (8 warps).
// B[k] (16KB bf16) staged ONCE in smem (pitch 516 uints, conflict-free);
// warp w owns m-tile rows [128*by + 16w, +16), A streamed from g_xbf (bf16,
// L2/L1-resident; 32KB per-warp footprint -> L1 hits after first touch).
// Per k16-step: 4 LDG.32 (A) + 4 LDS.32 (B) + 2 HMMA. No inner syncthreads.
// ---------------------------------------------------------------------------
__global__ void __launch_bounds__(256) mbd_gemm_kernel(
    const float* __restrict__ x, float* __restrict__ out)
{
    __shared__ unsigned int sw[16 * 516];       // 33 KB B tile

    const int tid  = threadIdx.x;
    const int lane = tid & 31;
    const int w    = tid >> 5;
    const int k    = blockIdx.x;
    const int b0   = blockIdx.y * 128 + w * 16;
    const int g    = lane >> 2;
    const int tig  = lane & 3;

    // ---- folded x-copy: 256 blocks x 1024 float4 covers all of x ----
    {
        const int flat = blockIdx.y * 32 + blockIdx.x;   // 0..255
        const float4* x4 = reinterpret_cast<const float4*>(x);
        float4*       o4 = reinterpret_cast<float4*>(out);
#pragma unroll
        for (int i = 0; i < 4; i++) {
            int idx = flat * 1024 + tid + i * 256;
            int r = idx >> 8;
            int c = idx & 255;
            o4[(size_t)r * (OUT_COLS / 4) + c] = x4[idx];
        }
    }

    // ---- stage B[k]: 8192 uints, 32 per thread, pitch 516 ----
#pragma unroll
    for (int i = 0; i < 32; i++) {
        int idx = tid + i * 256;
        int m = idx >> 9;
        int c = idx & 511;
        sw[m * 516 + c] = g_wtbf[(size_t)k * 8192 + idx];
    }
    __syncthreads();

    float c0 = 0.f, c1 = 0.f, c2 = 0.f, c3 = 0.f;
    float c4 = 0.f, c5 = 0.f, c6 = 0.f, c7 = 0.f;

    const unsigned int* gx = g_xbf;
    const size_t rA0 = (size_t)(b0 + g) * 512 + tig;
    const size_t rA1 = (size_t)(b0 + g + 8) * 512 + tig;
    const int ib0 = g * 516 + tig;
    const int ib1 = (g + 8) * 516 + tig;

#pragma unroll 4
    for (int d0 = 0; d0 < 512; d0 += 8) {
        unsigned int a0 = __ldg(gx + rA0 + d0);
        unsigned int a1 = __ldg(gx + rA1 + d0);
        unsigned int a2 = __ldg(gx + rA0 + d0 + 4);
        unsigned int a3 = __ldg(gx + rA1 + d0 + 4);
        unsigned int b00 = sw[ib0 + d0];
        unsigned int b01 = sw[ib0 + d0 + 4];
        unsigned int b10 = sw[ib1 + d0];
        unsigned int b11 = sw[ib1 + d0 + 4];
        MMA_BF16(c0, c1, c2, c3, a0, a1, a2, a3, b00, b01);
        MMA_BF16(c4, c5, c6, c7, a0, a1, a2, a3, b10, b11);
    }

    __half2* o1 = g_acth + ((size_t)k * BATCH + b0 + g) * 8;
    __half2* o2 = o1 + 8 * 8;
    o1[tig]     = __float22half2_rn(make_float2(c0, c1));
    o1[4 + tig] = __float22half2_rn(make_float2(c4, c5));
    o2[tig]     = __float22half2_rn(make_float2(c2, c3));
    o2[4 + tig] = __float22half2_rn(make_float2(c6, c7));
}

// ---------------------------------------------------------------------------
// Kernel B: symmetric pairwise (verbatim R13: half2, 2 cols/iter, dual h2exp,
// packed shfl col-reduce). grid = (32 k, 36 tile-pairs), block = 256.
// ---------------------------------------------------------------------------
__global__ void __launch_bounds__(256) mbd_pairwise_kernel()
{
    const int k    = blockIdx.x;
    const int tid  = threadIdx.x;
    const int lane = tid & 31;
    const int w    = tid >> 5;
    const int bsub = w & 3;
    const int ch   = w >> 2;
    const int2 pr  = c_pairs[blockIdx.y];
    const int i_t  = pr.x, j_t = pr.y;
    const bool diag = (i_t == j_t);

    __shared__ uint4 sA[128 * 2];
    __shared__ uint4 sB[128 * 2];
    __shared__ float scol[8][64];
    __shared__ float srow[256];

    const uint4* actk = reinterpret_cast<const uint4*>(
        g_acth + (size_t)k * BATCH * 8);

    sA[tid] = actk[(size_t)i_t * 256 + tid];
    sB[tid] = actk[(size_t)j_t * 256 + tid];
    reinterpret_cast<float*>(scol)[tid]       = 0.f;
    reinterpret_cast<float*>(scol)[tid + 256] = 0.f;
    __syncthreads();

    const int bl = bsub * 32 + lane;
    __half2 a[8];
    {
        uint4 p0 = sA[bl * 2 + 0];
        uint4 p1 = sA[bl * 2 + 1];
        a[0] = *reinterpret_cast<__half2*>(&p0.x);
        a[1] = *reinterpret_cast<__half2*>(&p0.y);
        a[2] = *reinterpret_cast<__half2*>(&p0.z);
        a[3] = *reinterpret_cast<__half2*>(&p0.w);
        a[4] = *reinterpret_cast<__half2*>(&p1.x);
        a[5] = *reinterpret_cast<__half2*>(&p1.y);
        a[6] = *reinterpret_cast<__half2*>(&p1.z);
        a[7] = *reinterpret_cast<__half2*>(&p1.w);
    }

    float f = 0.f;
    const int c_beg = ch * 64;

#define HAD(x, y) __habs2(__hsub2(x, y))
#define H2(u) (*reinterpret_cast<const __half2*>(&(u)))

#pragma unroll 4
    for (int cc = 0; cc < 32; cc++) {
        const int c0 = c_beg + 2 * cc;
        uint4 p0 = sB[c0 * 2 + 0];
        uint4 p1 = sB[c0 * 2 + 1];
        uint4 q0 = sB[c0 * 2 + 2];
        uint4 q1 = sB[c0 * 2 + 3];

        __half2 t0 = __hadd2(HAD(a[0], H2(p0.x)), HAD(a[1], H2(p0.y)));
        __half2 t1 = __hadd2(HAD(a[2], H2(p0.z)), HAD(a[3], H2(p0.w)));
        __half2 t2 = __hadd2(HAD(a[4], H2(p1.x)), HAD(a[5], H2(p1.y)));
        __half2 t3 = __hadd2(HAD(a[6], H2(p1.z)), HAD(a[7], H2(p1.w)));
        t0 = __hadd2(__hadd2(t0, t1), __hadd2(t2, t3));
        __half2 u0 = __hadd2(HAD(a[0], H2(q0.x)), HAD(a[1], H2(q0.y)));
        __half2 u1 = __hadd2(HAD(a[2], H2(q0.z)), HAD(a[3], H2(q0.w)));
        __half2 u2 = __hadd2(HAD(a[4], H2(q1.x)), HAD(a[5], H2(q1.y)));
        __half2 u3 = __hadd2(HAD(a[6], H2(q1.z)), HAD(a[7], H2(q1.w)));
        u0 = __hadd2(__hadd2(u0, u1), __hadd2(u2, u3));

        __half2 s2 = __hadd2(__lows2half2(t0, u0), __highs2half2(t0, u0));
        __half2 e2 = h2exp(__hneg2(s2));
        float2 ef = __half22float2(e2);
        f += ef.x + ef.y;

        if (!diag) {
            unsigned int ev = *reinterpret_cast<unsigned int*>(&e2);
#pragma unroll
            for (int m = 16; m >= 1; m >>= 1) {
                unsigned int ov = __shfl_xor_sync(0xffffffffu, ev, m);
                __half2 sum = __hadd2(*reinterpret_cast<__half2*>(&ev),
                                      *reinterpret_cast<__half2*>(&ov));
                ev = *reinterpret_cast<unsigned int*>(&sum);
            }
            if (lane == 0) {
                float2 cf = __half22float2(*reinterpret_cast<__half2*>(&ev));
                scol[w][2 * cc]     += cf.x;
                scol[w][2 * cc + 1] += cf.y;
            }
        }
    }
#undef HAD
#undef H2

    srow[tid] = f;
    __syncthreads();

    if (tid < 128) {
        float rt = srow[tid] + srow[tid + 128];
        g_pp[(((size_t)k * NTILE + i_t) * NTILE + j_t) * 128 + tid] = rt;
    }
    if (!diag && tid < 128) {
        const int c   = tid;
        const int cch = c >> 6;
        const int cl  = c & 63;
        float ct = scol[cch * 4 + 0][cl] + scol[cch * 4 + 1][cl]
                 + scol[cch * 4 + 2][cl] + scol[cch * 4 + 3][cl];
        g_pp[(((size_t)k * NTILE + j_t) * NTILE + i_t) * 128 + c] = ct;
    }
}

// ---------------------------------------------------------------------------
// Kernel C: assemble features from g_pp.
// ---------------------------------------------------------------------------
__global__ void __launch_bounds__(256) mbd_assemble_kernel(float* __restrict__ out)
{
    const int gtid = blockIdx.x * 256 + threadIdx.x;   // 0..32767
    const int k = gtid >> 10;
    const int b = gtid & 1023;
    const int t = b >> 7;
    const int r = b & 127;
    const float* pp = g_pp + (((size_t)k * NTILE + t) * NTILE) * 128 + r;
    float s = 0.f;
#pragma unroll
    for (int j = 0; j < NTILE; j++)
        s += pp[j * 128];
    out[(size_t)b * OUT_COLS + INPUT_DIM + k] = s;
}

extern "C" void kernel_launch(void* const* d_in, const int* in_sizes, int n_in,
                              void* d_out, int out_size)
{
    (void)in_sizes; (void)n_in; (void)out_size;
    const float* x = (const float*)d_in[0];
    const float* W = (const float*)d_in[1];
    float* out = (float*)d_out;

    mbd_convert_kernel<<<192, 256>>>(x, W);
    mbd_gemm_kernel<<<dim3(NB_K, NTILE), 256>>>(x, out);
    mbd_pairwise_kernel<<<dim3(NB_K, NPAIRS), 256>>>();
    mbd_assemble_kernel<<<NB_K * BATCH / 256, 256>>>(out);
}